// round 4
// baseline (speedup 1.0000x reference)
#include <cuda_runtime.h>

static constexpr int Bn   = 128;
static constexpr int Nn   = 256;
static constexpr int SMAX = 300;

// Per-batch partials: [0..Bn) = pair-loss sums, [Bn..2Bn) = setsize losses.
__device__ float    g_partials[2 * Bn];
__device__ unsigned g_count = 0;

__device__ __forceinline__ float fsqrt_ap(float x) {
    float r;
    asm("sqrt.approx.f32 %0, %1;" : "=f"(r) : "f"(x));
    return r;
}

// Warp-wide min for non-negative floats (u32 bit ordering == float ordering;
// NaN bit patterns are huge, so they lose the min — desired).
__device__ __forceinline__ float warp_min_nonneg(float x) {
    unsigned u = __float_as_uint(x), r;
    asm("redux.sync.min.u32 %0, %1, 0xffffffff;" : "=r"(r) : "r"(u));
    return __uint_as_float(r);
}

struct PairSmem {
    float2 comb[Nn * 15];   // [j*15 + cls*3 + chg] = {nllc+nllq+fe^2, fe}
    float4 fa[Nn];          // fx, fy, fz, |fpos|^2
    float4 fb[Nn];          // fmx, fmy, fmz, |fmom|^2
    float  colmin[4][Nn];   // per row-group column mins
    float  rq[4][Nn];       // per j-quarter row mins
    float  red[16];
};
struct SetSmem { float x[SMAX]; float red[16]; };
union FusedSmem { PairSmem p; SetSmem s; };

// ---------------------------------------------------------------------------
// Fully fused kernel, grid = 256 blocks x 512 threads.
//   blocks [0,128)   : pair loss for batch b
//   blocks [128,256) : setsize loss for batch b-128
// Pair block: 16 warps = 4 row-groups (64 rows: 2 rows/lane) x 4 j-quarters
// (64 cols). Uniform j per warp -> broadcast loads; redux colmin per 2 pairs.
// Last block (completion counter) reduces all partials to the scalar.
// ---------------------------------------------------------------------------
__global__ void __launch_bounds__(512, 2) fused_kernel(
    const int*   __restrict__ pcls,  const int*   __restrict__ pchg,
    const int*   __restrict__ n_part,
    const float* __restrict__ cl_logits, const float* __restrict__ ch_logits,
    const float* __restrict__ ppos,  const float* __restrict__ fpos,
    const float* __restrict__ pmom,  const float* __restrict__ fmom,
    const float* __restrict__ pe,    const float* __restrict__ fe,
    const float* __restrict__ pred,
    float* __restrict__ out)
{
    __shared__ FusedSmem sm;
    __shared__ unsigned  s_islast;
    __shared__ float     s_fin[8];
    const int t = threadIdx.x;

    if (blockIdx.x < Bn) {
        // ================= PAIR-LOSS BLOCK =================
        PairSmem& S = sm.p;
        const int b = blockIdx.x;

        // ---- stage pflow-side tables (threads 0..255, one per pflow j) ----
        if (t < Nn) {
            const int j  = t;
            const int gj = b * Nn + j;
            float nc[5], nq[3];
            {
                const float* cl = cl_logits + gj * 5;
                float x0 = cl[0], x1 = cl[1], x2 = cl[2], x3 = cl[3], x4 = cl[4];
                float m  = fmaxf(fmaxf(fmaxf(x0, x1), fmaxf(x2, x3)), x4);
                float s  = __expf(x0 - m) + __expf(x1 - m) + __expf(x2 - m)
                         + __expf(x3 - m) + __expf(x4 - m);
                float lse = m + __logf(s);
                nc[0] = lse - x0; nc[1] = lse - x1; nc[2] = lse - x2;
                nc[3] = lse - x3; nc[4] = lse - x4;
            }
            {
                const float* ch = ch_logits + gj * 3;
                float x0 = ch[0], x1 = ch[1], x2 = ch[2];
                float m  = fmaxf(fmaxf(x0, x1), x2);
                float s  = __expf(x0 - m) + __expf(x1 - m) + __expf(x2 - m);
                float lse = m + __logf(s);
                nq[0] = lse - x0; nq[1] = lse - x1; nq[2] = lse - x2;
            }
            float fx = fpos[gj * 3 + 0], fy = fpos[gj * 3 + 1], fz = fpos[gj * 3 + 2];
            float mx = fmom[gj * 3 + 0], my = fmom[gj * 3 + 1], mz = fmom[gj * 3 + 2];
            float fev = fe[gj];
            float np = fmaf(fx, fx, fmaf(fy, fy, fz * fz));
            float nm = fmaf(mx, mx, fmaf(my, my, mz * mz));
            float fe2 = fev * fev;
            S.fa[j] = make_float4(fx, fy, fz, np);
            S.fb[j] = make_float4(mx, my, mz, nm);
            #pragma unroll
            for (int c = 0; c < 5; c++)
                #pragma unroll
                for (int q = 0; q < 3; q++)
                    S.comb[j * 15 + c * 3 + q] = make_float2(nc[c] + nq[q] + fe2, fev);
        }

        // ---- per-thread: two particle rows in registers ----
        const int w    = t >> 5;
        const int lane = t & 31;
        const int r    = w & 3;        // row-group: rows [r*64, r*64+64)
        const int q    = w >> 2;       // j-quarter: cols [q*64, q*64+64)
        const int i0   = r * 64 + lane;
        const int i1   = i0 + 32;
        const int gi0  = b * Nn + i0;
        const int gi1  = b * Nn + i1;

        const int cc0 = pcls[gi0] * 3 + pchg[gi0];
        const int cc1 = pcls[gi1] * 3 + pchg[gi1];

        float px0 = ppos[gi0*3+0], py0 = ppos[gi0*3+1], pz0 = ppos[gi0*3+2];
        float qx0 = pmom[gi0*3+0], qy0 = pmom[gi0*3+1], qz0 = pmom[gi0*3+2];
        float pe0v = pe[gi0];
        float px1 = ppos[gi1*3+0], py1 = ppos[gi1*3+1], pz1 = ppos[gi1*3+2];
        float qx1 = pmom[gi1*3+0], qy1 = pmom[gi1*3+1], qz1 = pmom[gi1*3+2];
        float pe1v = pe[gi1];

        const float rp0 = fmaf(px0, px0, fmaf(py0, py0, pz0 * pz0));
        const float rm0 = fmaf(qx0, qx0, fmaf(qy0, qy0, qz0 * qz0));
        const float pe20 = pe0v * pe0v;
        const float m2x0 = -2.f*px0, m2y0 = -2.f*py0, m2z0 = -2.f*pz0;
        const float n2x0 = -2.f*qx0, n2y0 = -2.f*qy0, n2z0 = -2.f*qz0;
        const float m2e0 = -2.f*pe0v;
        const float rp1 = fmaf(px1, px1, fmaf(py1, py1, pz1 * pz1));
        const float rm1 = fmaf(qx1, qx1, fmaf(qy1, qy1, qz1 * qz1));
        const float pe21 = pe1v * pe1v;
        const float m2x1 = -2.f*px1, m2y1 = -2.f*py1, m2z1 = -2.f*pz1;
        const float n2x1 = -2.f*qx1, n2y1 = -2.f*qy1, n2z1 = -2.f*qz1;
        const float m2e1 = -2.f*pe1v;

        __syncthreads();

        float rowmin0 = 1e30f, rowmin1 = 1e30f;
        const int jend = q * 64 + 64;
        #pragma unroll 4
        for (int j = q * 64; j < jend; j++) {
            float4 a  = S.fa[j];
            float4 bb = S.fb[j];
            float2 c0 = S.comb[j * 15 + cc0];
            float2 c1 = S.comb[j * 15 + cc1];

            float d2p0 = rp0 + a.w;
            d2p0 = fmaf(m2x0, a.x, d2p0);
            d2p0 = fmaf(m2y0, a.y, d2p0);
            d2p0 = fmaf(m2z0, a.z, d2p0);
            float d2m0 = rm0 + bb.w;
            d2m0 = fmaf(n2x0, bb.x, d2m0);
            d2m0 = fmaf(n2y0, bb.y, d2m0);
            d2m0 = fmaf(n2z0, bb.z, d2m0);
            float l0 = fmaf(m2e0, c0.y, c0.x) + pe20;
            l0 += fsqrt_ap(d2p0) + fsqrt_ap(d2m0);
            rowmin0 = fminf(rowmin0, l0);

            float d2p1 = rp1 + a.w;
            d2p1 = fmaf(m2x1, a.x, d2p1);
            d2p1 = fmaf(m2y1, a.y, d2p1);
            d2p1 = fmaf(m2z1, a.z, d2p1);
            float d2m1 = rm1 + bb.w;
            d2m1 = fmaf(n2x1, bb.x, d2m1);
            d2m1 = fmaf(n2y1, bb.y, d2m1);
            d2m1 = fmaf(n2z1, bb.z, d2m1);
            float l1 = fmaf(m2e1, c1.y, c1.x) + pe21;
            l1 += fsqrt_ap(d2p1) + fsqrt_ap(d2m1);
            rowmin1 = fminf(rowmin1, l1);

            float cm = warp_min_nonneg(fminf(l0, l1));
            if (lane == 0) S.colmin[r][j] = cm;
        }
        S.rq[q][i0] = rowmin0;
        S.rq[q][i1] = rowmin1;
        __syncthreads();

        // ---- combine: sum_i rowmin_i + sum_j colmin_j, block reduce ----
        if (t < Nn) {
            float rm = fminf(fminf(S.rq[0][t], S.rq[1][t]),
                             fminf(S.rq[2][t], S.rq[3][t]));
            float cm = fminf(fminf(S.colmin[0][t], S.colmin[1][t]),
                             fminf(S.colmin[2][t], S.colmin[3][t]));
            float v = rm + cm;
            #pragma unroll
            for (int o = 16; o; o >>= 1) v += __shfl_xor_sync(0xffffffffu, v, o);
            if (lane == 0) S.red[t >> 5] = v;
        }
        __syncthreads();
        if (t == 0) {
            float s = 0.f;
            #pragma unroll
            for (int wv = 0; wv < 8; wv++) s += S.red[wv];
            g_partials[b] = s;
        }
    } else {
        // ================= SETSIZE BLOCK =================
        SetSmem& S = sm.s;
        const int b = blockIdx.x - Bn;
        const int warp = t >> 5, lane = t & 31;
        const bool act = t < SMAX;
        const float* base = pred + (size_t)b * Nn * SMAX;

        float a = 0.f;
        if (act) {
            #pragma unroll 4
            for (int n = 0; n < Nn; n++) a += base[n * SMAX + t];
            a *= (1.f / Nn);
            S.x[t] = a;
        }

        float v = act ? a : -1e30f;
        #pragma unroll
        for (int o = 16; o; o >>= 1) v = fmaxf(v, __shfl_xor_sync(0xffffffffu, v, o));
        if (lane == 0) S.red[warp] = v;
        __syncthreads();
        float m = S.red[0];
        #pragma unroll
        for (int wv = 1; wv < 16; wv++) m = fmaxf(m, S.red[wv]);

        float e = act ? __expf(a - m) : 0.f;
        #pragma unroll
        for (int o = 16; o; o >>= 1) e += __shfl_xor_sync(0xffffffffu, e, o);
        __syncthreads();
        if (lane == 0) S.red[warp] = e;
        __syncthreads();

        if (t == 0) {
            float Z = 0.f;
            #pragma unroll
            for (int wv = 0; wv < 16; wv++) Z += S.red[wv];
            float logZ = m + __logf(Z);
            g_partials[Bn + b] = logZ - S.x[n_part[b]];
        }
    }

    // ================= COMPLETION-COUNTER FINAL REDUCTION =================
    if (t == 0) {
        __threadfence();
        unsigned old = atomicAdd(&g_count, 1u);
        s_islast = (old == 2u * Bn - 1u) ? 1u : 0u;
    }
    __syncthreads();
    if (s_islast) {
        if (t < 2 * Bn) {
            float v = ((volatile float*)g_partials)[t];
            #pragma unroll
            for (int o = 16; o; o >>= 1) v += __shfl_xor_sync(0xffffffffu, v, o);
            if ((t & 31) == 0) s_fin[t >> 5] = v;
        }
        __syncthreads();
        if (t == 0) {
            float s = 0.f;
            #pragma unroll
            for (int wv = 0; wv < 8; wv++) s += s_fin[wv];
            out[0] = s * (1.0f / Bn);
            g_count = 0;   // reset for next graph replay
        }
    }
}

extern "C" void kernel_launch(void* const* d_in, const int* in_sizes, int n_in,
                              void* d_out, int out_size)
{
    const int*   pcls  = (const int*)  d_in[0];
    const int*   pchg  = (const int*)  d_in[1];
    const int*   npart = (const int*)  d_in[2];
    const float* cl    = (const float*)d_in[3];
    const float* ch    = (const float*)d_in[4];
    const float* ppos  = (const float*)d_in[5];
    const float* fpos  = (const float*)d_in[6];
    const float* pmom  = (const float*)d_in[7];
    const float* fmom  = (const float*)d_in[8];
    const float* pe    = (const float*)d_in[9];
    const float* fe    = (const float*)d_in[10];
    const float* pred  = (const float*)d_in[11];

    fused_kernel<<<2 * Bn, 512>>>(pcls, pchg, npart, cl, ch,
                                  ppos, fpos, pmom, fmom, pe, fe, pred,
                                  (float*)d_out);
}

// round 5
// speedup vs baseline: 1.2206x; 1.2206x over previous
#include <cuda_runtime.h>

static constexpr int Bn   = 128;
static constexpr int Nn   = 256;
static constexpr int SMAX = 300;

// Per-batch partials: [0..Bn) = pair-loss sums, [Bn..2Bn) = setsize losses.
__device__ float    g_partials[2 * Bn];
__device__ unsigned g_count = 0;

__device__ __forceinline__ float fsqrt_ap(float x) {
    float r;
    asm("sqrt.approx.f32 %0, %1;" : "=f"(r) : "f"(x));
    return r;
}

// Warp-wide min for non-negative floats (u32 bit ordering == float ordering;
// NaN bit patterns are huge, so they lose the min — desired).
__device__ __forceinline__ float warp_min_nonneg(float x) {
    unsigned u = __float_as_uint(x), r;
    asm("redux.sync.min.u32 %0, %1, 0xffffffff;" : "=r"(r) : "r"(u));
    return __uint_as_float(r);
}

struct PairSmem {
    float2 comb[Nn * 15];   // [j*15 + cls*3 + chg] = {nllc+nllq+fe^2, fe}
    float4 fa[Nn];          // fx, fy, fz, |fpos|^2
    float4 fb[Nn];          // fmx, fmy, fmz, |fmom|^2
    float  colmin[4][Nn];   // per row-group column mins
    float  rq[4][Nn];       // per j-quarter row mins
    float  red[16];
};
struct SetSmem { float x[SMAX]; float red[16]; };
union FusedSmem { PairSmem p; SetSmem s; };

// ---------------------------------------------------------------------------
// Fully fused kernel, grid = 256 blocks x 512 threads.
//   blocks [0,128)   : pair loss for batch b
//   blocks [128,256) : setsize loss for batch b-128 (16-deep MLP column sums)
// Last block (completion counter) reduces all partials to the scalar.
// ---------------------------------------------------------------------------
__global__ void __launch_bounds__(512, 2) fused_kernel(
    const int*   __restrict__ pcls,  const int*   __restrict__ pchg,
    const int*   __restrict__ n_part,
    const float* __restrict__ cl_logits, const float* __restrict__ ch_logits,
    const float* __restrict__ ppos,  const float* __restrict__ fpos,
    const float* __restrict__ pmom,  const float* __restrict__ fmom,
    const float* __restrict__ pe,    const float* __restrict__ fe,
    const float* __restrict__ pred,
    float* __restrict__ out)
{
    __shared__ FusedSmem sm;
    __shared__ unsigned  s_islast;
    __shared__ float     s_fin[8];
    const int t = threadIdx.x;

    if (blockIdx.x < Bn) {
        // ================= PAIR-LOSS BLOCK =================
        PairSmem& S = sm.p;
        const int b = blockIdx.x;

        // ---- stage pflow-side tables (threads 0..255, one per pflow j) ----
        if (t < Nn) {
            const int j  = t;
            const int gj = b * Nn + j;
            float nc[5], nq[3];
            {
                const float* cl = cl_logits + gj * 5;
                float x0 = cl[0], x1 = cl[1], x2 = cl[2], x3 = cl[3], x4 = cl[4];
                float m  = fmaxf(fmaxf(fmaxf(x0, x1), fmaxf(x2, x3)), x4);
                float s  = __expf(x0 - m) + __expf(x1 - m) + __expf(x2 - m)
                         + __expf(x3 - m) + __expf(x4 - m);
                float lse = m + __logf(s);
                nc[0] = lse - x0; nc[1] = lse - x1; nc[2] = lse - x2;
                nc[3] = lse - x3; nc[4] = lse - x4;
            }
            {
                const float* ch = ch_logits + gj * 3;
                float x0 = ch[0], x1 = ch[1], x2 = ch[2];
                float m  = fmaxf(fmaxf(x0, x1), x2);
                float s  = __expf(x0 - m) + __expf(x1 - m) + __expf(x2 - m);
                float lse = m + __logf(s);
                nq[0] = lse - x0; nq[1] = lse - x1; nq[2] = lse - x2;
            }
            float fx = fpos[gj * 3 + 0], fy = fpos[gj * 3 + 1], fz = fpos[gj * 3 + 2];
            float mx = fmom[gj * 3 + 0], my = fmom[gj * 3 + 1], mz = fmom[gj * 3 + 2];
            float fev = fe[gj];
            float np = fmaf(fx, fx, fmaf(fy, fy, fz * fz));
            float nm = fmaf(mx, mx, fmaf(my, my, mz * mz));
            float fe2 = fev * fev;
            S.fa[j] = make_float4(fx, fy, fz, np);
            S.fb[j] = make_float4(mx, my, mz, nm);
            #pragma unroll
            for (int c = 0; c < 5; c++)
                #pragma unroll
                for (int q = 0; q < 3; q++)
                    S.comb[j * 15 + c * 3 + q] = make_float2(nc[c] + nq[q] + fe2, fev);
        }

        // ---- per-thread: two particle rows in registers ----
        const int w    = t >> 5;
        const int lane = t & 31;
        const int r    = w & 3;        // row-group: rows [r*64, r*64+64)
        const int q    = w >> 2;       // j-quarter: cols [q*64, q*64+64)
        const int i0   = r * 64 + lane;
        const int i1   = i0 + 32;
        const int gi0  = b * Nn + i0;
        const int gi1  = b * Nn + i1;

        const int cc0 = pcls[gi0] * 3 + pchg[gi0];
        const int cc1 = pcls[gi1] * 3 + pchg[gi1];

        float px0 = ppos[gi0*3+0], py0 = ppos[gi0*3+1], pz0 = ppos[gi0*3+2];
        float qx0 = pmom[gi0*3+0], qy0 = pmom[gi0*3+1], qz0 = pmom[gi0*3+2];
        float pe0v = pe[gi0];
        float px1 = ppos[gi1*3+0], py1 = ppos[gi1*3+1], pz1 = ppos[gi1*3+2];
        float qx1 = pmom[gi1*3+0], qy1 = pmom[gi1*3+1], qz1 = pmom[gi1*3+2];
        float pe1v = pe[gi1];

        const float rp0 = fmaf(px0, px0, fmaf(py0, py0, pz0 * pz0));
        const float rm0 = fmaf(qx0, qx0, fmaf(qy0, qy0, qz0 * qz0));
        const float pe20 = pe0v * pe0v;
        const float m2x0 = -2.f*px0, m2y0 = -2.f*py0, m2z0 = -2.f*pz0;
        const float n2x0 = -2.f*qx0, n2y0 = -2.f*qy0, n2z0 = -2.f*qz0;
        const float m2e0 = -2.f*pe0v;
        const float rp1 = fmaf(px1, px1, fmaf(py1, py1, pz1 * pz1));
        const float rm1 = fmaf(qx1, qx1, fmaf(qy1, qy1, qz1 * qz1));
        const float pe21 = pe1v * pe1v;
        const float m2x1 = -2.f*px1, m2y1 = -2.f*py1, m2z1 = -2.f*pz1;
        const float n2x1 = -2.f*qx1, n2y1 = -2.f*qy1, n2z1 = -2.f*qz1;
        const float m2e1 = -2.f*pe1v;

        __syncthreads();

        float rowmin0 = 1e30f, rowmin1 = 1e30f;
        const int jend = q * 64 + 64;
        #pragma unroll 4
        for (int j = q * 64; j < jend; j++) {
            float4 a  = S.fa[j];
            float4 bb = S.fb[j];
            float2 c0 = S.comb[j * 15 + cc0];
            float2 c1 = S.comb[j * 15 + cc1];

            float d2p0 = rp0 + a.w;
            d2p0 = fmaf(m2x0, a.x, d2p0);
            d2p0 = fmaf(m2y0, a.y, d2p0);
            d2p0 = fmaf(m2z0, a.z, d2p0);
            float d2m0 = rm0 + bb.w;
            d2m0 = fmaf(n2x0, bb.x, d2m0);
            d2m0 = fmaf(n2y0, bb.y, d2m0);
            d2m0 = fmaf(n2z0, bb.z, d2m0);
            float l0 = fmaf(m2e0, c0.y, c0.x) + pe20;
            l0 += fsqrt_ap(d2p0) + fsqrt_ap(d2m0);
            rowmin0 = fminf(rowmin0, l0);

            float d2p1 = rp1 + a.w;
            d2p1 = fmaf(m2x1, a.x, d2p1);
            d2p1 = fmaf(m2y1, a.y, d2p1);
            d2p1 = fmaf(m2z1, a.z, d2p1);
            float d2m1 = rm1 + bb.w;
            d2m1 = fmaf(n2x1, bb.x, d2m1);
            d2m1 = fmaf(n2y1, bb.y, d2m1);
            d2m1 = fmaf(n2z1, bb.z, d2m1);
            float l1 = fmaf(m2e1, c1.y, c1.x) + pe21;
            l1 += fsqrt_ap(d2p1) + fsqrt_ap(d2m1);
            rowmin1 = fminf(rowmin1, l1);

            float cm = warp_min_nonneg(fminf(l0, l1));
            if (lane == 0) S.colmin[r][j] = cm;
        }
        S.rq[q][i0] = rowmin0;
        S.rq[q][i1] = rowmin1;
        __syncthreads();

        // ---- combine: sum_i rowmin_i + sum_j colmin_j, block reduce ----
        if (t < Nn) {
            float rm = fminf(fminf(S.rq[0][t], S.rq[1][t]),
                             fminf(S.rq[2][t], S.rq[3][t]));
            float cm = fminf(fminf(S.colmin[0][t], S.colmin[1][t]),
                             fminf(S.colmin[2][t], S.colmin[3][t]));
            float v = rm + cm;
            #pragma unroll
            for (int o = 16; o; o >>= 1) v += __shfl_xor_sync(0xffffffffu, v, o);
            if (lane == 0) S.red[t >> 5] = v;
        }
        __syncthreads();
        if (t == 0) {
            float s = 0.f;
            #pragma unroll
            for (int wv = 0; wv < 8; wv++) s += S.red[wv];
            g_partials[b] = s;
        }
    } else {
        // ================= SETSIZE BLOCK =================
        // Column sums over N=256 rows with 16 loads in flight per thread
        // (previously unroll-4 -> 64 serialized DRAM round-trips was the
        // whole-kernel bottleneck).
        SetSmem& S = sm.s;
        const int b = blockIdx.x - Bn;
        const int warp = t >> 5, lane = t & 31;
        const bool act = t < SMAX;
        const float* base = pred + (size_t)b * Nn * SMAX;

        float a = 0.f;
        if (act) {
            float acc0 = 0.f, acc1 = 0.f, acc2 = 0.f, acc3 = 0.f;
            for (int n = 0; n < Nn; n += 16) {
                float v[16];
                #pragma unroll
                for (int k = 0; k < 16; k++)
                    v[k] = base[(size_t)(n + k) * SMAX + t];
                #pragma unroll
                for (int k = 0; k < 16; k += 4) {
                    acc0 += v[k + 0];
                    acc1 += v[k + 1];
                    acc2 += v[k + 2];
                    acc3 += v[k + 3];
                }
            }
            a = ((acc0 + acc1) + (acc2 + acc3)) * (1.f / Nn);
            S.x[t] = a;
        }

        float v = act ? a : -1e30f;
        #pragma unroll
        for (int o = 16; o; o >>= 1) v = fmaxf(v, __shfl_xor_sync(0xffffffffu, v, o));
        if (lane == 0) S.red[warp] = v;
        __syncthreads();
        float m = S.red[0];
        #pragma unroll
        for (int wv = 1; wv < 16; wv++) m = fmaxf(m, S.red[wv]);

        float e = act ? __expf(a - m) : 0.f;
        #pragma unroll
        for (int o = 16; o; o >>= 1) e += __shfl_xor_sync(0xffffffffu, e, o);
        __syncthreads();
        if (lane == 0) S.red[warp] = e;
        __syncthreads();

        if (t == 0) {
            float Z = 0.f;
            #pragma unroll
            for (int wv = 0; wv < 16; wv++) Z += S.red[wv];
            float logZ = m + __logf(Z);
            g_partials[Bn + b] = logZ - S.x[n_part[b]];
        }
    }

    // ================= COMPLETION-COUNTER FINAL REDUCTION =================
    if (t == 0) {
        __threadfence();
        unsigned old = atomicAdd(&g_count, 1u);
        s_islast = (old == 2u * Bn - 1u) ? 1u : 0u;
    }
    __syncthreads();
    if (s_islast) {
        if (t < 2 * Bn) {
            float v = ((volatile float*)g_partials)[t];
            #pragma unroll
            for (int o = 16; o; o >>= 1) v += __shfl_xor_sync(0xffffffffu, v, o);
            if ((t & 31) == 0) s_fin[t >> 5] = v;
        }
        __syncthreads();
        if (t == 0) {
            float s = 0.f;
            #pragma unroll
            for (int wv = 0; wv < 8; wv++) s += s_fin[wv];
            out[0] = s * (1.0f / Bn);
            g_count = 0;   // reset for next graph replay
        }
    }
}

extern "C" void kernel_launch(void* const* d_in, const int* in_sizes, int n_in,
                              void* d_out, int out_size)
{
    const int*   pcls  = (const int*)  d_in[0];
    const int*   pchg  = (const int*)  d_in[1];
    const int*   npart = (const int*)  d_in[2];
    const float* cl    = (const float*)d_in[3];
    const float* ch    = (const float*)d_in[4];
    const float* ppos  = (const float*)d_in[5];
    const float* fpos  = (const float*)d_in[6];
    const float* pmom  = (const float*)d_in[7];
    const float* fmom  = (const float*)d_in[8];
    const float* pe    = (const float*)d_in[9];
    const float* fe    = (const float*)d_in[10];
    const float* pred  = (const float*)d_in[11];

    fused_kernel<<<2 * Bn, 512>>>(pcls, pchg, npart, cl, ch,
                                  ppos, fpos, pmom, fmom, pe, fe, pred,
                                  (float*)d_out);
}